// round 17
// baseline (speedup 1.0000x reference)
#include <cuda_runtime.h>
#include <cuda_bf16.h>

// ---------------------------------------------------------------------------
// BaseGNN: 3-layer GCN, N=100000, E=1.6M, B=64. Persistent mega-kernel.
// R16: 519us (pre-scaled rows, unweighted sum; issue 29%). R17: HALF-WARP
// PER NODE gather — row = 256B = 16 lanes x uint4; one LDG.128 serves one
// edge of each of 2 nodes; width-16 shuffles; zero-row (index N_MAX) padding
// kills remainder-tail latency and inter-half divergence. bf16 storage,
// tf32 GEMM, 8 even grid barriers (sense self-resets per replay).
// ---------------------------------------------------------------------------

#define N_MAX 100000
#define E_MAX 1600000
#define NB    64
#define HID   128
#define OUTD  256
#define NBLK  592
#define NTHR  256
#define NWARP (NBLK * 8)
#define NHW   (NWARP * 2)          // half-warps

__device__ int   g_deg[N_MAX];
__device__ int   g_rowptr[N_MAX + 1];
__device__ int   g_cursor[N_MAX];
__device__ int   g_edge[E_MAX];    // src only (rows pre-scaled by dinv)
__device__ __nv_bfloat16 g_bufA[(size_t)(N_MAX + 1) * HID];   // +1: zero row
__device__ __nv_bfloat16 g_res [(size_t)(N_MAX + 1) * HID];
__device__ __nv_bfloat16 g_hbuf[(size_t)(N_MAX + 1) * HID];
__device__ float g_pool[NB * HID];
__device__ int   g_cnt[NB];
__device__ unsigned g_bar_count = 0;
__device__ unsigned g_bar_sense = 0;

__device__ __forceinline__ void grid_barrier(unsigned& ls) {
    __threadfence();
    __syncthreads();
    ls ^= 1u;
    if (threadIdx.x == 0) {
        unsigned arrived = atomicAdd(&g_bar_count, 1u);
        if (arrived == NBLK - 1u) {
            atomicExch(&g_bar_count, 0u);
            __threadfence();
            atomicExch(&g_bar_sense, ls);
        } else {
            while (((volatile unsigned*)&g_bar_sense)[0] != ls) __nanosleep(64);
            __threadfence();
        }
    }
    __syncthreads();
}

// ---------------------------------------------------------------------------
__device__ __forceinline__ unsigned long long mk_policy() {
    unsigned long long p;
    asm("createpolicy.fractional.L2::evict_last.b64 %0, 1.0;" : "=l"(p));
    return p;
}
__device__ __forceinline__ uint4 ldg_u4(const __nv_bfloat16* p, unsigned long long pol) {
    uint4 v;
    asm volatile("ld.global.L2::cache_hint.v4.u32 {%0,%1,%2,%3}, [%4], %5;"
                 : "=r"(v.x), "=r"(v.y), "=r"(v.z), "=r"(v.w) : "l"(p), "l"(pol));
    return v;
}
__device__ __forceinline__ void stg_u4(__nv_bfloat16* p, uint4 u, unsigned long long pol) {
    asm volatile("st.global.L2::cache_hint.v4.u32 [%0], {%1,%2,%3,%4}, %5;"
                 :: "l"(p), "r"(u.x), "r"(u.y), "r"(u.z), "r"(u.w), "l"(pol) : "memory");
}
__device__ __forceinline__ void stg_u4_plain(__nv_bfloat16* p, uint4 u) {
    *(uint4*)p = u;
}
__device__ __forceinline__ void stg_bf2(__nv_bfloat16* p, float a, float b, unsigned long long pol) {
    __nv_bfloat162 bb = __floats2bfloat162_rn(a, b);
    unsigned u = *reinterpret_cast<unsigned*>(&bb);
    asm volatile("st.global.L2::cache_hint.b32 [%0], %1, %2;"
                 :: "l"(p), "r"(u), "l"(pol) : "memory");
}
__device__ __forceinline__ void acc8_add(float* a, uint4 u) {
    float2 f;
    f = __bfloat1622float2(*(__nv_bfloat162*)&u.x); a[0] += f.x; a[1] += f.y;
    f = __bfloat1622float2(*(__nv_bfloat162*)&u.y); a[2] += f.x; a[3] += f.y;
    f = __bfloat1622float2(*(__nv_bfloat162*)&u.z); a[4] += f.x; a[5] += f.y;
    f = __bfloat1622float2(*(__nv_bfloat162*)&u.w); a[6] += f.x; a[7] += f.y;
}
__device__ __forceinline__ uint4 pack_bf8(const float* o) {
    uint4 u;
    __nv_bfloat162 b;
    b = __floats2bfloat162_rn(o[0], o[1]); u.x = *(unsigned*)&b;
    b = __floats2bfloat162_rn(o[2], o[3]); u.y = *(unsigned*)&b;
    b = __floats2bfloat162_rn(o[4], o[5]); u.z = *(unsigned*)&b;
    b = __floats2bfloat162_rn(o[6], o[7]); u.w = *(unsigned*)&b;
    return u;
}

// ---------------------------------------------------------------------------
// Half-warp gather: 16-edge groups, batches of 4, zero-row padded (no guards).
__device__ __forceinline__ void gather16(const __nv_bfloat16* __restrict__ h, int ll,
                                         int start, int end, int maxdeg,
                                         float* acc, unsigned long long pol) {
    int gmax = (maxdeg + 15) >> 4;
    for (int g = 0; g < gmax; g++) {
        int e0 = start + (g << 4);
        int rec = (e0 + ll < end) ? g_edge[e0 + ll] : N_MAX;
        int cmax = min(16, maxdeg - (g << 4));
        cmax = (cmax + 3) & ~3;               // pad to 4 (zero row absorbs)
        for (int j = 0; j < cmax; j += 4) {
            int s0 = __shfl_sync(0xffffffffu, rec, j + 0, 16);
            int s1 = __shfl_sync(0xffffffffu, rec, j + 1, 16);
            int s2 = __shfl_sync(0xffffffffu, rec, j + 2, 16);
            int s3 = __shfl_sync(0xffffffffu, rec, j + 3, 16);
            uint4 u0 = ldg_u4(h + (size_t)s0 * HID + ll * 8, pol);
            uint4 u1 = ldg_u4(h + (size_t)s1 * HID + ll * 8, pol);
            uint4 u2 = ldg_u4(h + (size_t)s2 * HID + ll * 8, pol);
            uint4 u3 = ldg_u4(h + (size_t)s3 * HID + ll * 8, pol);
            acc8_add(acc, u0); acc8_add(acc, u1);
            acc8_add(acc, u2); acc8_add(acc, u3);
        }
    }
}

// ---------------------------------------------------------------------------
// Aggregate + LN phase, half-warp per node.
// RESID_X: residual = x@rW+rb (sW = rW|rb in smem); else bf16 rbuf row.
template<bool RESID_X, bool SCALE_OUT>
__device__ void agg_ln_phase(const __nv_bfloat16* __restrict__ h,
                             const float* __restrict__ xsrc,
                             const __nv_bfloat16* __restrict__ rbuf,
                             const float* __restrict__ bias, const float* __restrict__ gam,
                             const float* __restrict__ bet, __nv_bfloat16* __restrict__ outp,
                             int n, int gwarp, int lane, const float* sW,
                             unsigned long long pol) {
    int hl = lane >> 4, ll = lane & 15;
    for (int nb = gwarp * 2; nb < n; nb += 2 * NWARP) {       // warp-uniform
        int node = nb + hl;
        bool valid = node < n;
        int nd = valid ? node : N_MAX;
        int start = 0, end = 0;
        if (valid) { start = g_rowptr[node]; end = g_rowptr[node + 1]; }
        int deg = end - start;
        int maxdeg = max(deg, __shfl_xor_sync(0xffffffffu, deg, 16));
        float acc[8] = {0.f, 0.f, 0.f, 0.f, 0.f, 0.f, 0.f, 0.f};
        acc8_add(acc, ldg_u4(h + (size_t)nd * HID + ll * 8, pol));  // self
        gather16(h, ll, start, end, maxdeg, acc, pol);
        float dinv = rsqrtf((float)(deg + 1));
        #pragma unroll
        for (int i = 0; i < 8; i++) acc[i] *= dinv;
        // residual
        float rr[8];
        if (RESID_X) {
            #pragma unroll
            for (int i = 0; i < 8; i++) rr[i] = sW[20 * 128 + ll * 8 + i];
            float xva = xsrc[(size_t)(valid ? node : 0) * 20 + ll];
            float xvb = (ll < 4) ? xsrc[(size_t)(valid ? node : 0) * 20 + 16 + ll] : 0.f;
            #pragma unroll
            for (int k = 0; k < 16; k++) {
                float xk = __shfl_sync(0xffffffffu, xva, k, 16);
                #pragma unroll
                for (int i = 0; i < 8; i++) rr[i] += xk * sW[k * 128 + ll * 8 + i];
            }
            #pragma unroll
            for (int k = 0; k < 4; k++) {
                float xk = __shfl_sync(0xffffffffu, xvb, k, 16);
                #pragma unroll
                for (int i = 0; i < 8; i++) rr[i] += xk * sW[(16 + k) * 128 + ll * 8 + i];
            }
        } else {
            #pragma unroll
            for (int i = 0; i < 8; i++) rr[i] = 0.f;
            acc8_add(rr, ldg_u4(rbuf + (size_t)nd * HID + ll * 8, pol));
        }
        // bias + LN + ReLU
        float v[8], s = 0.f, sq = 0.f;
        #pragma unroll
        for (int i = 0; i < 8; i++) {
            v[i] = acc[i] + rr[i] + bias[ll * 8 + i];
            s += v[i]; sq += v[i] * v[i];
        }
        #pragma unroll
        for (int off = 8; off > 0; off >>= 1) {
            s  += __shfl_xor_sync(0xffffffffu, s,  off, 16);
            sq += __shfl_xor_sync(0xffffffffu, sq, off, 16);
        }
        float mu  = s * (1.f / HID);
        float var = sq * (1.f / HID) - mu * mu;
        float rs  = rsqrtf(var + 1e-5f);
        float o[8];
        #pragma unroll
        for (int i = 0; i < 8; i++) {
            o[i] = fmaxf(0.f, (v[i] - mu) * rs * gam[ll * 8 + i] + bet[ll * 8 + i]);
            if (SCALE_OUT) o[i] *= dinv;
        }
        if (valid) {
            uint4 u = pack_bf8(o);
            if (SCALE_OUT) stg_u4(outp + (size_t)node * HID + ll * 8, u, pol);
            else           stg_u4_plain(outp + (size_t)node * HID + ll * 8, u);
        }
    }
}

// ---------------------------------------------------------------------------
// tf32 helpers
__device__ __forceinline__ unsigned f2tf(float f) {
    unsigned r;
    asm("cvt.rna.tf32.f32 %0, %1;" : "=r"(r) : "f"(f));
    return r;
}
__device__ __forceinline__ float4 ldg_bf4_plain(const __nv_bfloat16* p) {
    const __nv_bfloat162* q = (const __nv_bfloat162*)p;
    float2 f0 = __bfloat1622float2(q[0]);
    float2 f1 = __bfloat1622float2(q[1]);
    return make_float4(f0.x, f0.y, f1.x, f1.y);
}
__device__ __forceinline__ void mma_tf32(float& d0, float& d1, float& d2, float& d3,
                                         unsigned a0, unsigned a1, unsigned a2, unsigned a3,
                                         unsigned b0, unsigned b1) {
    asm volatile(
        "mma.sync.aligned.m16n8k8.row.col.f32.tf32.tf32.f32 "
        "{%0,%1,%2,%3}, {%4,%5,%6,%7}, {%8,%9}, {%0,%1,%2,%3};\n"
        : "+f"(d0), "+f"(d1), "+f"(d2), "+f"(d3)
        : "r"(a0), "r"(a1), "r"(a2), "r"(a3), "r"(b0), "r"(b1));
}

// GEMM phase: C[n,128] = A_bf16[n,128] @ W[128,128]; tf32 MMA; output rows
// pre-scaled by dinv[row] (next gather operand), stored bf16 evict_last.
__device__ void gemm_phase128(const __nv_bfloat16* __restrict__ A, const float* __restrict__ W,
                              __nv_bfloat16* __restrict__ C, int n, float* sh,
                              unsigned long long pol) {
    const int rowTiles = (n + 63) >> 6;
    const int ntiles = rowTiles * 2;
    float (*As)[68] = (float(*)[68])sh;              // [32][68] (k-major)
    float (*Ws)[64] = (float(*)[64])(sh + 32 * 68);  // [32][64]
    int tid = threadIdx.x;
    int lane = tid & 31, wid = tid >> 5;
    int wr = (wid & 3) * 16;
    int wc = (wid >> 2) * 32;
    int frow = lane >> 2;
    int fcol = lane & 3;
    for (int t = blockIdx.x; t < ntiles; t += NBLK) {
        int row0 = (t % rowTiles) << 6;
        int col0 = (t / rowTiles) << 6;
        float d[4][4];
        #pragma unroll
        for (int nt = 0; nt < 4; nt++)
            #pragma unroll
            for (int q = 0; q < 4; q++) d[nt][q] = 0.f;
        #pragma unroll
        for (int k0 = 0; k0 < 128; k0 += 32) {
            #pragma unroll
            for (int l = tid; l < 64 * 8; l += NTHR) {
                int m = l >> 3, k4 = l & 7;
                int r = row0 + m;
                float4 v = (r < n) ? ldg_bf4_plain(A + (size_t)r * 128 + k0 + k4 * 4)
                                   : make_float4(0.f, 0.f, 0.f, 0.f);
                As[k4 * 4 + 0][m] = v.x;
                As[k4 * 4 + 1][m] = v.y;
                As[k4 * 4 + 2][m] = v.z;
                As[k4 * 4 + 3][m] = v.w;
            }
            #pragma unroll
            for (int l = tid; l < 32 * 16; l += NTHR) {
                int k = l >> 4, c4 = l & 15;
                float4 v = ((const float4*)(W + (size_t)(k0 + k) * 128 + col0))[c4];
                ((float4*)&Ws[k][c4 * 4])[0] = v;
            }
            __syncthreads();
            #pragma unroll
            for (int kk = 0; kk < 32; kk += 8) {
                int ak = kk + fcol;
                int ar = wr + frow;
                unsigned a0 = f2tf(As[ak    ][ar    ]);
                unsigned a1 = f2tf(As[ak    ][ar + 8]);
                unsigned a2 = f2tf(As[ak + 4][ar    ]);
                unsigned a3 = f2tf(As[ak + 4][ar + 8]);
                #pragma unroll
                for (int nt = 0; nt < 4; nt++) {
                    int bc = wc + nt * 8 + frow;
                    unsigned b0 = f2tf(Ws[ak    ][bc]);
                    unsigned b1 = f2tf(Ws[ak + 4][bc]);
                    mma_tf32(d[nt][0], d[nt][1], d[nt][2], d[nt][3],
                             a0, a1, a2, a3, b0, b1);
                }
            }
            __syncthreads();
        }
        int r = row0 + wr + frow;
        float di0 = (r < n)     ? rsqrtf((float)(g_deg[r] + 1))     : 0.f;
        float di1 = (r + 8 < n) ? rsqrtf((float)(g_deg[r + 8] + 1)) : 0.f;
        #pragma unroll
        for (int nt = 0; nt < 4; nt++) {
            int c = col0 + wc + nt * 8 + fcol * 2;
            if (r < n)     stg_bf2(C + (size_t)r * 128 + c,       d[nt][0] * di0, d[nt][1] * di0, pol);
            if (r + 8 < n) stg_bf2(C + (size_t)(r + 8) * 128 + c, d[nt][2] * di1, d[nt][3] * di1, pol);
        }
    }
}

// ---------------------------------------------------------------------------
__global__ void __launch_bounds__(NTHR, 4) mega_kernel(
    const float* __restrict__ x, const int* __restrict__ src,
    const int* __restrict__ dst, const int* __restrict__ batch,
    const float* __restrict__ W1, const float* __restrict__ b1,
    const float* __restrict__ W2, const float* __restrict__ b2,
    const float* __restrict__ W3, const float* __restrict__ b3,
    const float* __restrict__ rW, const float* __restrict__ rb,
    const float* __restrict__ g1, const float* __restrict__ be1,
    const float* __restrict__ g2, const float* __restrict__ be2,
    float* __restrict__ out, int n, int e)
{
    __shared__ float sh[5248];
    unsigned ls = 0;
    const unsigned long long pol = mk_policy();
    const int tid  = threadIdx.x;
    const int gtid = blockIdx.x * NTHR + tid;
    const int gstr = NBLK * NTHR;
    const int lane = tid & 31, wid = tid >> 5;
    const int gwarp = blockIdx.x * 8 + wid;

    // ---- P0: zero (incl. zero rows at index N_MAX) ----
    for (int i = gtid; i < n; i += gstr) g_deg[i] = 0;
    if (gtid < NB) g_cnt[gtid] = 0;
    for (int i = gtid; i < NB * HID; i += gstr) g_pool[i] = 0.f;
    if (gtid < HID) {
        __nv_bfloat16 z = __float2bfloat16(0.f);
        g_bufA[(size_t)N_MAX * HID + gtid] = z;
        g_res [(size_t)N_MAX * HID + gtid] = z;
        g_hbuf[(size_t)N_MAX * HID + gtid] = z;
    }
    grid_barrier(ls);                                            // B1

    // ---- P1: histograms ----
    for (int i = gtid; i < e; i += gstr) atomicAdd(&g_deg[dst[i]], 1);
    for (int i = gtid; i < n; i += gstr) atomicAdd(&g_cnt[batch[i]], 1);
    grid_barrier(ls);                                            // B2

    // ---- P2: block 0 scans (4 elems/thread); others: W1 GEMM, rows scaled ----
    if (blockIdx.x == 0) {
        int* wsum = (int*)sh;
        int carry = 0;
        for (int base = 0; base < n; base += NTHR * 4) {
            int i0 = base + tid * 4;
            int v0 = (i0 + 0 < n) ? g_deg[i0 + 0] : 0;
            int v1 = (i0 + 1 < n) ? g_deg[i0 + 1] : 0;
            int v2 = (i0 + 2 < n) ? g_deg[i0 + 2] : 0;
            int v3 = (i0 + 3 < n) ? g_deg[i0 + 3] : 0;
            int tsum = v0 + v1 + v2 + v3;
            int xv = tsum;
            #pragma unroll
            for (int off = 1; off < 32; off <<= 1) {
                int t = __shfl_up_sync(0xffffffffu, xv, off);
                if (lane >= off) xv += t;
            }
            if (lane == 31) wsum[wid] = xv;
            __syncthreads();
            if (wid == 0) {
                int sv = (lane < 8) ? wsum[lane] : 0;
                #pragma unroll
                for (int off = 1; off < 8; off <<= 1) {
                    int t = __shfl_up_sync(0xffffffffu, sv, off);
                    if (lane >= off) sv += t;
                }
                if (lane < 8) wsum[lane] = sv;
            }
            __syncthreads();
            int excl = carry + (wid ? wsum[wid - 1] : 0) + xv - tsum;
            if (i0 + 0 < n) { g_rowptr[i0 + 0] = excl;                g_cursor[i0 + 0] = excl; }
            if (i0 + 1 < n) { g_rowptr[i0 + 1] = excl + v0;           g_cursor[i0 + 1] = excl + v0; }
            if (i0 + 2 < n) { g_rowptr[i0 + 2] = excl + v0 + v1;      g_cursor[i0 + 2] = excl + v0 + v1; }
            if (i0 + 3 < n) { g_rowptr[i0 + 3] = excl + v0 + v1 + v2; g_cursor[i0 + 3] = excl + v0 + v1 + v2; }
            int total = wsum[7];
            __syncthreads();
            carry += total;
        }
        if (tid == 0) g_rowptr[n] = carry;
    } else {
        float* sW1 = sh;            // 2560 floats
        for (int i = tid; i < 20 * 128; i += NTHR) sW1[i] = W1[i];
        __syncthreads();
        int w2 = (blockIdx.x - 1) * 8 + wid;
        for (int row = w2; row < n; row += (NBLK - 1) * 8) {
            float xv = (lane < 20) ? x[(size_t)row * 20 + lane] : 0.f;
            float4 a = make_float4(0.f, 0.f, 0.f, 0.f);
            #pragma unroll
            for (int k = 0; k < 20; k++) {
                float xk = __shfl_sync(0xffffffffu, xv, k);
                float4 w = ((const float4*)(sW1 + k * 128))[lane];
                a.x += xk * w.x; a.y += xk * w.y; a.z += xk * w.z; a.w += xk * w.w;
            }
            float dinv = rsqrtf((float)(g_deg[row] + 1));
            a.x *= dinv; a.y *= dinv; a.z *= dinv; a.w *= dinv;
            __nv_bfloat162 b0 = __floats2bfloat162_rn(a.x, a.y);
            __nv_bfloat162 b1 = __floats2bfloat162_rn(a.z, a.w);
            unsigned lo = *reinterpret_cast<unsigned*>(&b0);
            unsigned hi = *reinterpret_cast<unsigned*>(&b1);
            asm volatile("st.global.L2::cache_hint.v2.u32 [%0], {%1,%2}, %3;"
                         :: "l"(g_bufA + (size_t)row * HID + lane * 4),
                            "r"(lo), "r"(hi), "l"(pol) : "memory");
        }
    }
    grid_barrier(ls);                                            // B3

    // ---- P3: csr fill (src only) ----
    for (int i = gtid; i < e; i += gstr) {
        int s = src[i], d = dst[i];
        int pos = atomicAdd(&g_cursor[d], 1);
        g_edge[pos] = s;
    }
    grid_barrier(ls);                                            // B4

    // ---- layer 1: agg-sum + dinv + (x@rW+rb) residual + LN + ReLU ----
    {
        for (int i = tid; i < 20 * 128; i += NTHR) sh[i] = rW[i];
        if (tid < 128) sh[20 * 128 + tid] = rb[tid];
        __syncthreads();
        agg_ln_phase<true, false>(g_bufA, x, nullptr, b1, g1, be1, g_hbuf, n, gwarp, lane, sh, pol);
    }
    grid_barrier(ls);                                            // B5

    // ---- layer 2 GEMM (tf32, output rows pre-scaled by dinv) ----
    gemm_phase128(g_hbuf, W2, g_bufA, n, sh, pol);
    grid_barrier(ls);                                            // B6

    agg_ln_phase<false, true>(g_bufA, nullptr, g_hbuf, b2, g2, be2, g_res, n, gwarp, lane, nullptr, pol);
    grid_barrier(ls);                                            // B7

    // ---- layer 3: agg-sum + pool fused (contiguous chunk per half-warp) ----
    {
        int hl = lane >> 4, ll = lane & 15;
        int ch = (n + NHW - 1) / NHW;
        int ghw = gwarp * 2 + hl;
        int lo = ghw * ch;
        int hi = min(n, lo + ch);
        float pacc[8] = {0.f, 0.f, 0.f, 0.f, 0.f, 0.f, 0.f, 0.f};
        int cur = (lo < n) ? batch[lo] : 0;
        for (int it = 0; it < ch; it++) {                       // warp-uniform
            int node = lo + it;
            bool valid = node < hi;
            int nd = valid ? node : N_MAX;
            int start = 0, end = 0;
            if (valid) { start = g_rowptr[node]; end = g_rowptr[node + 1]; }
            int deg = end - start;
            int maxdeg = max(deg, __shfl_xor_sync(0xffffffffu, deg, 16));
            float acc[8] = {0.f, 0.f, 0.f, 0.f, 0.f, 0.f, 0.f, 0.f};
            acc8_add(acc, ldg_u4(g_res + (size_t)nd * HID + ll * 8, pol));
            gather16(g_res, ll, start, end, maxdeg, acc, pol);
            float dinv = rsqrtf((float)(deg + 1));
            if (valid) {
                int g = batch[node];
                if (g != cur) {
                    float* p = &g_pool[cur * HID + ll * 8];
                    #pragma unroll
                    for (int i = 0; i < 8; i++) atomicAdd(p + i, pacc[i]);
                    #pragma unroll
                    for (int i = 0; i < 8; i++) pacc[i] = 0.f;
                    cur = g;
                }
                #pragma unroll
                for (int i = 0; i < 8; i++) pacc[i] += acc[i] * dinv;
            }
        }
        if (lo < n) {
            float* p = &g_pool[cur * HID + ll * 8];
            #pragma unroll
            for (int i = 0; i < 8; i++) atomicAdd(p + i, pacc[i]);
        }
    }
    grid_barrier(ls);                                            // B8 (even count)

    // ---- final: out[b,:] = (pool[b,:]/cnt[b]) @ W3 + b3 (blocks 0..63) ----
    if (blockIdx.x < NB) {
        int b = blockIdx.x;
        float* sp = sh;               // 128 floats
        float c = (float)g_cnt[b];
        float inv = (c > 0.f) ? 1.f / c : 0.f;
        if (tid < 128) sp[tid] = g_pool[b * HID + tid] * inv;
        __syncthreads();
        float acc = 0.f;
        #pragma unroll 8
        for (int k = 0; k < 128; k++)
            acc += sp[k] * W3[(size_t)k * OUTD + tid];
        out[b * OUTD + tid] = (c > 0.f) ? (acc + b3[tid]) : 0.f;
    }
}

// ---------------------------------------------------------------------------
extern "C" void kernel_launch(void* const* d_in, const int* in_sizes, int n_in,
                              void* d_out, int out_size) {
    const float* x     = (const float*)d_in[0];
    const int*   ei    = (const int*)d_in[1];      // int32 (JAX x64 disabled)
    const int*   batch = (const int*)d_in[2];
    const float *W1 = (const float*)d_in[3],  *b1 = (const float*)d_in[4];
    const float *W2 = (const float*)d_in[5],  *b2 = (const float*)d_in[6];
    const float *W3 = (const float*)d_in[7],  *b3 = (const float*)d_in[8];
    const float *rW = (const float*)d_in[9],  *rb = (const float*)d_in[10];
    const float *g1 = (const float*)d_in[11], *be1 = (const float*)d_in[12];
    const float *g2 = (const float*)d_in[13], *be2 = (const float*)d_in[14];
    float* out = (float*)d_out;

    int n = in_sizes[0] / 20;
    int e = in_sizes[1] / 2;
    const int* src = ei;
    const int* dst = ei + e;

    mega_kernel<<<NBLK, NTHR>>>(x, src, dst, batch,
                                W1, b1, W2, b2, W3, b3, rW, rb,
                                g1, be1, g2, be2, out, n, e);
}